// round 10
// baseline (speedup 1.0000x reference)
#include <cuda_runtime.h>
#include <cstdint>

#define N_DENSE   13
#define N_FIELDS  26
#define PER_FIELD 100000
#define FEATURE_NUM 2600013   // 26*100000 + 13
#define BATCH 4096

#define ROWS_PER_BLOCK 4
#define THREADS 256           // 8 warps = 4 rows x 2 sub-warps

// L2 cache-policy load on the generic path.
__device__ __forceinline__ float ldg_pol(const float* p, uint64_t pol) {
    float v;
    asm volatile("ld.global.L2::cache_hint.f32 %0, [%1], %2;"
                 : "=f"(v) : "l"(p), "l"(pol));
    return v;
}

__global__ __launch_bounds__(THREADS, 7)
void fm_kernel(const float* __restrict__ dense,   // [B, 13]
               const int*   __restrict__ sparse,  // [B, 26]
               const float* __restrict__ w0,      // [1]
               const float* __restrict__ w,       // [FEATURE_NUM, 1]
               const float* __restrict__ V,       // [16, FEATURE_NUM]
               float*       __restrict__ out)     // [B, 1]
{
    __shared__ float s_e [ROWS_PER_BLOCK][16];
    __shared__ float s_sq[ROWS_PER_BLOCK][16];
    __shared__ float s_f [ROWS_PER_BLOCK];

    const int warp      = threadIdx.x >> 5;
    const int lane      = threadIdx.x & 31;
    const int row_local = warp >> 1;
    const int sub       = warp & 1;          // 0: fields 0-13 + dense, 1: fields 14-25
    const int row       = blockIdx.x * ROWS_PER_BLOCK + row_local;

    const int k    = lane & 15;              // latent dim for this lane
    const int half = lane >> 4;

    // k < 8  -> evict_last  (pin: resident across graph replays, ~68 MB incl. w)
    // k >= 8 -> evict_first (stream: preferred victim, never displaces pinned)
    uint64_t pol_first, pol_last;
    asm("createpolicy.fractional.L2::evict_first.b64 %0, 1.0;" : "=l"(pol_first));
    asm("createpolicy.fractional.L2::evict_last.b64  %0, 1.0;" : "=l"(pol_last));
    const uint64_t pol_v = (k < 8) ? pol_last : pol_first;

    // preload the row's 26 global indices (lane j < 26 holds idx_j)
    int myidx = 0;
    if (lane < N_FIELDS)
        myidx = N_DENSE + lane * PER_FIELD + sparse[row * N_FIELDS + lane];
    float myd = (lane < N_DENSE) ? dense[row * N_DENSE + lane] : 0.f;

    const float* __restrict__ Vk = V + (size_t)k * FEATURE_NUM;

    float e = 0.f, sq = 0.f;
    if (sub == 0) {
        // fields j = half + 2t, t = 0..6 -> j in 0..13 ; 7 independent LDGs/lane
        #pragma unroll
        for (int t = 0; t < 7; ++t) {
            const int j = half + 2 * t;
            const int g = __shfl_sync(0xffffffffu, myidx, j);
            const float v = ldg_pol(Vk + g, pol_v);
            e  += v;
            sq += v * v;
        }
        // dense part: tiny hot region
        #pragma unroll
        for (int d = 0; d < N_DENSE; ++d) {
            const float dd = __shfl_sync(0xffffffffu, myd, d);
            const float vk = Vk[d];
            if (half == 0) {
                e  += dd * vk;
                sq += (dd * dd) * (vk * vk);
            }
        }
    } else {
        // fields j = half + 2t, t = 7..12 -> j in 14..25 ; 6 independent LDGs/lane
        #pragma unroll
        for (int t = 7; t < 13; ++t) {
            const int j = half + 2 * t;
            const int g = __shfl_sync(0xffffffffu, myidx, j);
            const float v = ldg_pol(Vk + g, pol_v);
            e  += v;
            sq += v * v;
        }
    }

    // merge halves within warp -> every lane holds partial e[k], sq[k]
    e  += __shfl_xor_sync(0xffffffffu, e, 16);
    sq += __shfl_xor_sync(0xffffffffu, sq, 16);

    // first order partial (w table ~7.6 MB of lines: pin it)
    float f = 0.f;
    if (sub == 0) {
        if (lane < N_DENSE) f = ldg_pol(w + myidx, pol_last) + myd * w[lane];
    } else {
        if (lane >= N_DENSE && lane < N_FIELDS) f = ldg_pol(w + myidx, pol_last);
    }
    #pragma unroll
    for (int s = 16; s >= 1; s >>= 1)
        f += __shfl_xor_sync(0xffffffffu, f, s);

    // cross-warp combine via smem
    if (sub == 1) {
        if (lane < 16) {
            s_e [row_local][lane] = e;
            s_sq[row_local][lane] = sq;
        }
        if (lane == 0) s_f[row_local] = f;
    }
    __syncthreads();

    if (sub == 0) {
        const float et = e  + s_e [row_local][k];
        const float st = sq + s_sq[row_local][k];
        float t2 = et * et - st;
        #pragma unroll
        for (int s = 8; s >= 1; s >>= 1)
            t2 += __shfl_xor_sync(0xffffffffu, t2, s);
        if (lane == 0)
            out[row] = w0[0] + f + s_f[row_local] + 0.5f * t2;
    }
}

extern "C" void kernel_launch(void* const* d_in, const int* in_sizes, int n_in,
                              void* d_out, int out_size)
{
    const float* dense  = (const float*)d_in[0];
    const int*   sparse = (const int*)  d_in[1];
    const float* w0     = (const float*)d_in[2];
    const float* w      = (const float*)d_in[3];
    const float* V      = (const float*)d_in[4];
    float* out = (float*)d_out;

    const int blocks = BATCH / ROWS_PER_BLOCK;   // 1024
    fm_kernel<<<blocks, THREADS>>>(dense, sparse, w0, w, V, out);
}

// round 11
// speedup vs baseline: 1.2759x; 1.2759x over previous
#include <cuda_runtime.h>
#include <cstdint>

#define N_DENSE   13
#define N_FIELDS  26
#define PER_FIELD 100000
#define FEATURE_NUM 2600013   // 26*100000 + 13
#define BATCH 4096

#define ROWS_PER_BLOCK 4
#define THREADS 256           // 8 warps = 4 rows x 2 sub-warps

// evict_first policy load on the generic L2 path. Used for the streaming slice of V.
__device__ __forceinline__ float ldg_stream(const float* p, uint64_t pol) {
    float v;
    asm volatile("ld.global.L2::cache_hint.f32 %0, [%1], %2;"
                 : "=f"(v) : "l"(p), "l"(pol));
    return v;
}

__global__ __launch_bounds__(THREADS, 7)
void fm_kernel(const float* __restrict__ dense,   // [B, 13]
               const int*   __restrict__ sparse,  // [B, 26]
               const float* __restrict__ w0,      // [1]
               const float* __restrict__ w,       // [FEATURE_NUM, 1]
               const float* __restrict__ V,       // [16, FEATURE_NUM]
               float*       __restrict__ out)     // [B, 1]
{
    __shared__ float s_e [ROWS_PER_BLOCK][16];
    __shared__ float s_sq[ROWS_PER_BLOCK][16];
    __shared__ float s_f [ROWS_PER_BLOCK];

    const int warp      = threadIdx.x >> 5;
    const int lane      = threadIdx.x & 31;
    const int row_local = warp >> 1;
    const int sub       = warp & 1;          // 0: fields 0-13 + dense, 1: fields 14-25
    const int row       = blockIdx.x * ROWS_PER_BLOCK + row_local;

    const int k    = lane & 15;              // latent dim for this lane
    const int half = lane >> 4;

    // k >= 6 -> stream (evict_first, preferred victim).
    // Resident set = 6 V-planes (45.6 MB) + w (7.6 MB) ~= 53 MB (42% of L2),
    // default policy -> should persist across graph replays via plain LRU.
    const bool stream_lane = (k >= 6);
    uint64_t pol_first;
    asm("createpolicy.fractional.L2::evict_first.b64 %0, 1.0;" : "=l"(pol_first));

    // preload the row's 26 global indices (lane j < 26 holds idx_j)
    int myidx = 0;
    if (lane < N_FIELDS)
        myidx = N_DENSE + lane * PER_FIELD + sparse[row * N_FIELDS + lane];
    float myd = (lane < N_DENSE) ? dense[row * N_DENSE + lane] : 0.f;

    const float* __restrict__ Vk = V + (size_t)k * FEATURE_NUM;

    float e = 0.f, sq = 0.f;
    if (sub == 0) {
        // fields j = half + 2t, t = 0..6 -> j in 0..13 ; 7 independent LDGs/lane
        #pragma unroll
        for (int t = 0; t < 7; ++t) {
            const int j = half + 2 * t;
            const int g = __shfl_sync(0xffffffffu, myidx, j);
            const float v = stream_lane ? ldg_stream(Vk + g, pol_first) : Vk[g];
            e  += v;
            sq += v * v;
        }
        // dense part: tiny hot region
        #pragma unroll
        for (int d = 0; d < N_DENSE; ++d) {
            const float dd = __shfl_sync(0xffffffffu, myd, d);
            const float vk = Vk[d];
            if (half == 0) {
                e  += dd * vk;
                sq += (dd * dd) * (vk * vk);
            }
        }
    } else {
        // fields j = half + 2t, t = 7..12 -> j in 14..25 ; 6 independent LDGs/lane
        #pragma unroll
        for (int t = 7; t < 13; ++t) {
            const int j = half + 2 * t;
            const int g = __shfl_sync(0xffffffffu, myidx, j);
            const float v = stream_lane ? ldg_stream(Vk + g, pol_first) : Vk[g];
            e  += v;
            sq += v * v;
        }
    }

    // merge halves within warp -> every lane holds partial e[k], sq[k]
    e  += __shfl_xor_sync(0xffffffffu, e, 16);
    sq += __shfl_xor_sync(0xffffffffu, sq, 16);

    // first order partial (w table: default policy, resident)
    float f = 0.f;
    if (sub == 0) {
        if (lane < N_DENSE) f = w[myidx] + myd * w[lane];
    } else {
        if (lane >= N_DENSE && lane < N_FIELDS) f = w[myidx];
    }
    #pragma unroll
    for (int s = 16; s >= 1; s >>= 1)
        f += __shfl_xor_sync(0xffffffffu, f, s);

    // cross-warp combine via smem
    if (sub == 1) {
        if (lane < 16) {
            s_e [row_local][lane] = e;
            s_sq[row_local][lane] = sq;
        }
        if (lane == 0) s_f[row_local] = f;
    }
    __syncthreads();

    if (sub == 0) {
        const float et = e  + s_e [row_local][k];
        const float st = sq + s_sq[row_local][k];
        float t2 = et * et - st;
        #pragma unroll
        for (int s = 8; s >= 1; s >>= 1)
            t2 += __shfl_xor_sync(0xffffffffu, t2, s);
        if (lane == 0)
            out[row] = w0[0] + f + s_f[row_local] + 0.5f * t2;
    }
}

extern "C" void kernel_launch(void* const* d_in, const int* in_sizes, int n_in,
                              void* d_out, int out_size)
{
    const float* dense  = (const float*)d_in[0];
    const int*   sparse = (const int*)  d_in[1];
    const float* w0     = (const float*)d_in[2];
    const float* w      = (const float*)d_in[3];
    const float* V      = (const float*)d_in[4];
    float* out = (float*)d_out;

    const int blocks = BATCH / ROWS_PER_BLOCK;   // 1024
    fm_kernel<<<blocks, THREADS>>>(dense, sparse, w0, w, V, out);
}